// round 2
// baseline (speedup 1.0000x reference)
#include <cuda_runtime.h>
#include <math.h>

#define S 4096
#define E 768
#define Hh 12
#define D 64
#define Wb 256
#define TT 513          // band width 2W+1
#define TP 516          // padded band row stride
#define TQ 32           // query rows per CTA
#define NKB 9           // 64-wide key blocks covering [q0-256, q0+320)
#define NEGV -1000000000.0f
#define SCALE 0.125f    // 1/sqrt(64)

// ---------------- scratch (static __device__, no allocations) ----------------
__device__ float g_q [S*E];
__device__ float g_k [S*E];
__device__ float g_v [S*E];
__device__ float g_cq[S*E];
__device__ float g_ck[S*E];
__device__ float g_lam[S*Hh];

// ---------------- projection GEMM: C = (A @ W + b) * scale ----------------
// BM=128, BN=128, BK=16, 256 threads, 8x8 outputs per thread.
// blockIdx.z selects which of the 5 projections (fused launch).
#define BM 128
#define BN 128
#define BK 16

__global__ __launch_bounds__(256, 2) void gemm5_kernel(
    const float* __restrict__ hs, const float* __restrict__ ce,
    const float* __restrict__ Wq,  const float* __restrict__ bq,
    const float* __restrict__ Wk,  const float* __restrict__ bk,
    const float* __restrict__ Wv,  const float* __restrict__ bv,
    const float* __restrict__ Wcq, const float* __restrict__ bcq,
    const float* __restrict__ Wck, const float* __restrict__ bck)
{
    const int which = blockIdx.z;
    const float* A;
    const float* Wt;
    const float* bias;
    float scale = 1.0f;
    float* C;
    switch (which) {
        case 0: A = hs; Wt = Wq;  bias = bq;  C = g_q;  break;
        case 1: A = hs; Wt = Wk;  bias = bk;  C = g_k;  break;
        case 2: A = hs; Wt = Wv;  bias = bv;  C = g_v;  break;
        case 3: A = ce; Wt = Wcq; bias = bcq; C = g_cq; scale = SCALE; break;
        default:A = ce; Wt = Wck; bias = bck; C = g_ck; break;
    }

    __shared__ float sA[BK][BM + 4];   // A^T tile
    __shared__ float sB[BK][BN];

    const int tid = threadIdx.x;
    const int m0 = blockIdx.y * BM;
    const int n0 = blockIdx.x * BN;
    const int rg = tid >> 4;            // 0..15 -> rows rg*8..rg*8+7
    const int cg = tid & 15;            // 0..15 -> cols cg*8..cg*8+7
    const int la_m = tid >> 1;          // 0..127
    const int la_k = (tid & 1) << 3;    // 0 or 8
    const int lb_k = tid >> 4;          // 0..15
    const int lb_n = (tid & 15) << 3;   // 0..120

    float acc[8][8];
    #pragma unroll
    for (int i = 0; i < 8; i++)
        #pragma unroll
        for (int j = 0; j < 8; j++) acc[i][j] = 0.f;

    for (int k0 = 0; k0 < E; k0 += BK) {
        float4 a0 = *(const float4*)&A[(size_t)(m0 + la_m) * E + k0 + la_k];
        float4 a1 = *(const float4*)&A[(size_t)(m0 + la_m) * E + k0 + la_k + 4];
        float4 b0 = *(const float4*)&Wt[(size_t)(k0 + lb_k) * E + n0 + lb_n];
        float4 b1 = *(const float4*)&Wt[(size_t)(k0 + lb_k) * E + n0 + lb_n + 4];
        sA[la_k + 0][la_m] = a0.x; sA[la_k + 1][la_m] = a0.y;
        sA[la_k + 2][la_m] = a0.z; sA[la_k + 3][la_m] = a0.w;
        sA[la_k + 4][la_m] = a1.x; sA[la_k + 5][la_m] = a1.y;
        sA[la_k + 6][la_m] = a1.z; sA[la_k + 7][la_m] = a1.w;
        *(float4*)&sB[lb_k][lb_n]     = b0;
        *(float4*)&sB[lb_k][lb_n + 4] = b1;
        __syncthreads();
        #pragma unroll
        for (int kk = 0; kk < BK; kk++) {
            float4 af0 = *(const float4*)&sA[kk][rg * 8];
            float4 af1 = *(const float4*)&sA[kk][rg * 8 + 4];
            float4 bf0 = *(const float4*)&sB[kk][cg * 8];
            float4 bf1 = *(const float4*)&sB[kk][cg * 8 + 4];
            float a_[8] = {af0.x, af0.y, af0.z, af0.w, af1.x, af1.y, af1.z, af1.w};
            float b_[8] = {bf0.x, bf0.y, bf0.z, bf0.w, bf1.x, bf1.y, bf1.z, bf1.w};
            #pragma unroll
            for (int i = 0; i < 8; i++)
                #pragma unroll
                for (int j = 0; j < 8; j++)
                    acc[i][j] += a_[i] * b_[j];
        }
        __syncthreads();
    }

    float4 bv0 = *(const float4*)&bias[n0 + cg * 8];
    float4 bv1 = *(const float4*)&bias[n0 + cg * 8 + 4];
    float bb[8] = {bv0.x, bv0.y, bv0.z, bv0.w, bv1.x, bv1.y, bv1.z, bv1.w};
    #pragma unroll
    for (int i = 0; i < 8; i++) {
        int m = m0 + rg * 8 + i;
        float4 o0, o1;
        o0.x = (acc[i][0] + bb[0]) * scale;
        o0.y = (acc[i][1] + bb[1]) * scale;
        o0.z = (acc[i][2] + bb[2]) * scale;
        o0.w = (acc[i][3] + bb[3]) * scale;
        o1.x = (acc[i][4] + bb[4]) * scale;
        o1.y = (acc[i][5] + bb[5]) * scale;
        o1.z = (acc[i][6] + bb[6]) * scale;
        o1.w = (acc[i][7] + bb[7]) * scale;
        *(float4*)&C[(size_t)m * E + n0 + cg * 8]     = o0;
        *(float4*)&C[(size_t)m * E + n0 + cg * 8 + 4] = o1;
    }
}

// ---------------- lam = 1 - sigmoid(cq.Wlqc + q.Wlqq + b) - sigmoid(ck.Wlkc + k.Wlkk + b) ----------------
__global__ __launch_bounds__(256) void lam_kernel(
    const float* __restrict__ Wlqc, const float* __restrict__ blqc,
    const float* __restrict__ Wlqq, const float* __restrict__ blqq,
    const float* __restrict__ Wlkc, const float* __restrict__ blkc,
    const float* __restrict__ Wlkk, const float* __restrict__ blkk)
{
    int gw   = (blockIdx.x * blockDim.x + threadIdx.x) >> 5;
    int lane = threadIdx.x & 31;
    if (gw >= S * Hh) return;
    int s = gw / Hh, h = gw % Hh;
    size_t base = (size_t)s * E + h * D;

    float a = g_cq[base + lane] * Wlqc[lane] + g_cq[base + lane + 32] * Wlqc[lane + 32]
            + g_q [base + lane] * Wlqq[lane] + g_q [base + lane + 32] * Wlqq[lane + 32];
    float b = g_ck[base + lane] * Wlkc[lane] + g_ck[base + lane + 32] * Wlkc[lane + 32]
            + g_k [base + lane] * Wlkk[lane] + g_k [base + lane + 32] * Wlkk[lane + 32];
    #pragma unroll
    for (int o = 16; o; o >>= 1) {
        a += __shfl_xor_sync(0xffffffffu, a, o);
        b += __shfl_xor_sync(0xffffffffu, b, o);
    }
    if (lane == 0) {
        float lq = 1.f / (1.f + __expf(-(a + blqc[0] + blqq[0])));
        float lk = 1.f / (1.f + __expf(-(b + blkc[0] + blkk[0])));
        g_lam[gw] = 1.f - lq - lk;
    }
}

// ---------------- fused band attention ----------------
// NOTE: g_cq holds cq * SCALE (pre-scaled by projection); quasi uses it as both
// query and key, matching the reference which scales cq before _band_qk(cq, cq).
// smem layout (floats):
//   sQT  [64][32]   @ 0      (q^T, pre-scaled)
//   sCQT [64][32]   @ 2048   (cq^T)
//   sKT  [64][64]   @ 4096   (k^T in QK phase; v [c][d] in PV phase)
//   sCKT [64][64]   @ 8192   (cq key-block^T)
//   sA   [32][516]  @ 12288  (attn band -> new_probs band)
//   sSg  [32][516]  @ 28800  (sigmoid(quasi) band)
//   sFm  [64]       @ 45312  (key mask additive)
#define SMEM_FLOATS 45376

__global__ __launch_bounds__(256, 1) void band_kernel(
    const int* __restrict__ amask, float* __restrict__ outp, float* __restrict__ npout)
{
    extern __shared__ float sm[];
    float* sQT  = sm;
    float* sCQT = sm + 2048;
    float* sKT  = sm + 4096;
    float* sCKT = sm + 8192;
    float* sA   = sm + 12288;
    float* sSg  = sm + 28800;
    float* sFm  = sm + 45312;

    const int h   = blockIdx.y;
    const int q0  = blockIdx.x * TQ;
    const int tid = threadIdx.x;

    // init band buffers: invalid -> NEG (attn), 0 (sigmoid(quasi))
    for (int i = tid; i < TQ * TP; i += 256) { sA[i] = NEGV; sSg[i] = 0.f; }

    // load query tiles (transposed); q scaled here, cq already scaled by projection
    {
        int r  = tid >> 3;
        int d0 = (tid & 7) << 3;
        const float* qp  = g_q  + (size_t)(q0 + r) * E + h * D + d0;
        const float* cqp = g_cq + (size_t)(q0 + r) * E + h * D + d0;
        #pragma unroll
        for (int u = 0; u < 8; u++) {
            sQT [(d0 + u) * TQ + r] = qp[u] * SCALE;
            sCQT[(d0 + u) * TQ + r] = cqp[u];
        }
    }
    __syncthreads();

    const int rg = tid >> 4, cg = tid & 15;
    const int r0s = rg << 1, c0s = cg << 2;

    // -------- QK + quasi-QK over 9 key blocks --------
    for (int b = 0; b < NKB; b++) {
        int kb0 = q0 - Wb + b * 64;
        {
            int c  = tid >> 2;
            int d0 = (tid & 3) << 4;
            int j  = kb0 + c;
            bool ok = (j >= 0) && (j < S);
            const float* kp = g_k  + (size_t)(ok ? j : 0) * E + h * D + d0;
            const float* cp = g_cq + (size_t)(ok ? j : 0) * E + h * D + d0;
            #pragma unroll
            for (int u = 0; u < 16; u++) {
                sKT [(d0 + u) * 64 + c] = ok ? kp[u] : 0.f;
                sCKT[(d0 + u) * 64 + c] = ok ? cp[u] : 0.f;
            }
            if (tid < 64) {
                int jj = kb0 + tid;
                sFm[tid] = (jj >= 0 && jj < S && amask[jj] != 0) ? -10000.f : 0.f;
            }
        }
        __syncthreads();

        float acc [2][4] = {{0.f,0.f,0.f,0.f},{0.f,0.f,0.f,0.f}};
        float accq[2][4] = {{0.f,0.f,0.f,0.f},{0.f,0.f,0.f,0.f}};
        #pragma unroll 8
        for (int kk = 0; kk < 64; kk++) {
            float2 qv  = *(const float2*)&sQT [kk * TQ + r0s];
            float2 cqv = *(const float2*)&sCQT[kk * TQ + r0s];
            float4 kv  = *(const float4*)&sKT [kk * 64 + c0s];
            float4 ckv = *(const float4*)&sCKT[kk * 64 + c0s];
            acc[0][0] += qv.x * kv.x;  acc[0][1] += qv.x * kv.y;
            acc[0][2] += qv.x * kv.z;  acc[0][3] += qv.x * kv.w;
            acc[1][0] += qv.y * kv.x;  acc[1][1] += qv.y * kv.y;
            acc[1][2] += qv.y * kv.z;  acc[1][3] += qv.y * kv.w;
            accq[0][0] += cqv.x * ckv.x; accq[0][1] += cqv.x * ckv.y;
            accq[0][2] += cqv.x * ckv.z; accq[0][3] += cqv.x * ckv.w;
            accq[1][0] += cqv.y * ckv.x; accq[1][1] += cqv.y * ckv.y;
            accq[1][2] += cqv.y * ckv.z; accq[1][3] += cqv.y * ckv.w;
        }

        int tbase = b * 64;
        #pragma unroll
        for (int i = 0; i < 2; i++) {
            int r = r0s + i;
            #pragma unroll
            for (int jx = 0; jx < 4; jx++) {
                int c = c0s + jx;
                int t = tbase + c - r;
                int j = kb0 + c;
                if (t >= 0 && t <= 512 && j >= 0 && j < S) {
                    float fm = sFm[c];
                    sA[r * TP + t] = acc[i][jx] + fm;
                    float qsc = accq[i][jx] + fm;
                    sSg[r * TP + t] = 1.f / (1.f + __expf(-qsc));
                }
            }
        }
        __syncthreads();
    }

    // -------- softmax + combine + write new_probs --------
    {
        int warp = tid >> 5, lane = tid & 31;
        for (int r = warp; r < TQ; r += 8) {
            int ig = q0 + r;
            float* arow = sA + r * TP;
            float m = NEGV;
            for (int t = lane; t < TT; t += 32) m = fmaxf(m, arow[t]);
            #pragma unroll
            for (int o = 16; o; o >>= 1) m = fmaxf(m, __shfl_xor_sync(0xffffffffu, m, o));
            float ssum = 0.f;
            for (int t = lane; t < TT; t += 32) ssum += __expf(arow[t] - m);
            #pragma unroll
            for (int o = 16; o; o >>= 1) ssum += __shfl_xor_sync(0xffffffffu, ssum, o);
            float inv  = 1.f / ssum;
            float lamv = g_lam[ig * Hh + h];
            bool  qm   = (amask[ig] != 0);
            float* nprow = npout + ((size_t)ig * Hh + h) * TT;
            for (int t = lane; t < TT; t += 32) {
                float p  = __expf(arow[t] - m) * inv;
                float np = p + lamv * sSg[r * TP + t];
                np = qm ? 0.f : np;
                arow[t]  = np;     // keep for PV
                nprow[t] = np;     // global output
            }
        }
    }
    __syncthreads();

    // -------- PV: out[r][d] = sum_t np[r][t] * v[j][d] --------
    {
        int r  = tid >> 3;
        int d0 = (tid & 7) << 3;
        float acc[8] = {0.f,0.f,0.f,0.f,0.f,0.f,0.f,0.f};
        for (int b = 0; b < NKB; b++) {
            int kb0 = q0 - Wb + b * 64;
            {
                int c  = tid >> 2;
                int dd = (tid & 3) << 4;
                int j  = kb0 + c;
                bool ok = (j >= 0) && (j < S);
                const float* vp = g_v + (size_t)(ok ? j : 0) * E + h * D + dd;
                #pragma unroll
                for (int u = 0; u < 16; u += 4) {
                    float4 x = ok ? *(const float4*)&vp[u] : make_float4(0.f, 0.f, 0.f, 0.f);
                    *(float4*)&sKT[c * 64 + dd + u] = x;
                }
            }
            __syncthreads();
            int tb = b * 64 - r;
            const float* arow = sA + r * TP;
            #pragma unroll 4
            for (int c = 0; c < 64; c++) {
                int t  = tb + c;
                int tc = t < 0 ? 0 : (t > 512 ? 512 : t);
                float p = arow[tc];
                if (t != tc) p = 0.f;
                float4 v0 = *(const float4*)&sKT[c * 64 + d0];
                float4 v1 = *(const float4*)&sKT[c * 64 + d0 + 4];
                acc[0] += p * v0.x; acc[1] += p * v0.y;
                acc[2] += p * v0.z; acc[3] += p * v0.w;
                acc[4] += p * v1.x; acc[5] += p * v1.y;
                acc[6] += p * v1.z; acc[7] += p * v1.w;
            }
            __syncthreads();
        }
        float* op = outp + (size_t)(q0 + r) * E + h * D + d0;
        #pragma unroll
        for (int u = 0; u < 8; u++) op[u] = acc[u];
    }
}

// ---------------- launch ----------------
extern "C" void kernel_launch(void* const* d_in, const int* in_sizes, int n_in,
                              void* d_out, int out_size)
{
    (void)in_sizes; (void)n_in; (void)out_size;

    const float* hs    = (const float*)d_in[0];
    const float* ce    = (const float*)d_in[1];
    const int*   amask = (const int*)  d_in[2];
    // d_in[3] is is_index_masked == (attention_mask != 0); derived from amask instead.
    const float* Wq   = (const float*)d_in[4];
    const float* bq   = (const float*)d_in[5];
    const float* Wk   = (const float*)d_in[6];
    const float* bk   = (const float*)d_in[7];
    const float* Wv   = (const float*)d_in[8];
    const float* bv   = (const float*)d_in[9];
    const float* Wcq  = (const float*)d_in[10];
    const float* bcq  = (const float*)d_in[11];
    const float* Wck  = (const float*)d_in[12];
    const float* bck  = (const float*)d_in[13];
    const float* Wlqc = (const float*)d_in[14];
    const float* blqc = (const float*)d_in[15];
    const float* Wlqq = (const float*)d_in[16];
    const float* blqq = (const float*)d_in[17];
    const float* Wlkc = (const float*)d_in[18];
    const float* blkc = (const float*)d_in[19];
    const float* Wlkk = (const float*)d_in[20];
    const float* blkk = (const float*)d_in[21];

    float* outp  = (float*)d_out;
    float* npout = outp + (size_t)S * E;   // tuple output: [out | new_probs]

    cudaFuncSetAttribute(band_kernel, cudaFuncAttributeMaxDynamicSharedMemorySize,
                         SMEM_FLOATS * 4);

    dim3 gg(E / BN, S / BM, 5);
    gemm5_kernel<<<gg, 256>>>(hs, ce, Wq, bq, Wk, bk, Wv, bv, Wcq, bcq, Wck, bck);

    lam_kernel<<<(S * Hh) / 8, 256>>>(Wlqc, blqc, Wlqq, blqq, Wlkc, blkc, Wlkk, blkk);

    band_kernel<<<dim3(S / TQ, Hh), 256, SMEM_FLOATS * 4>>>(amask, outp, npout);
}

// round 3
// speedup vs baseline: 1.4059x; 1.4059x over previous
#include <cuda_runtime.h>
#include <math.h>

#define S 4096
#define E 768
#define Hh 12
#define D 64
#define Wb 256
#define TT 513          // band width 2W+1
#define TQ 32           // query rows per CTA
#define NKB 9           // 64-wide key blocks covering [q0-256, q0+320)
#define NEGV -1000000000.0f
#define SCALE 0.125f    // 1/sqrt(64)

// ---------------- scratch (static __device__, no allocations) ----------------
__device__ float g_q [S*E];
__device__ float g_k [S*E];
__device__ float g_v [S*E];
__device__ float g_cq[S*E];
__device__ float g_ck[S*E];
__device__ float g_lam[S*Hh];

// ---------------- projection GEMM: C = (A @ W + b) * scale ----------------
#define BM 128
#define BN 128
#define BK 16

__global__ __launch_bounds__(256, 2) void gemm5_kernel(
    const float* __restrict__ hs, const float* __restrict__ ce,
    const float* __restrict__ Wq,  const float* __restrict__ bq,
    const float* __restrict__ Wk,  const float* __restrict__ bk,
    const float* __restrict__ Wv,  const float* __restrict__ bv,
    const float* __restrict__ Wcq, const float* __restrict__ bcq,
    const float* __restrict__ Wck, const float* __restrict__ bck)
{
    const int which = blockIdx.z;
    const float* A;
    const float* Wt;
    const float* bias;
    float scale = 1.0f;
    float* C;
    switch (which) {
        case 0: A = hs; Wt = Wq;  bias = bq;  C = g_q;  break;
        case 1: A = hs; Wt = Wk;  bias = bk;  C = g_k;  break;
        case 2: A = hs; Wt = Wv;  bias = bv;  C = g_v;  break;
        case 3: A = ce; Wt = Wcq; bias = bcq; C = g_cq; scale = SCALE; break;
        default:A = ce; Wt = Wck; bias = bck; C = g_ck; break;
    }

    __shared__ float sA[BK][BM + 4];   // A^T tile
    __shared__ float sB[BK][BN];

    const int tid = threadIdx.x;
    const int m0 = blockIdx.y * BM;
    const int n0 = blockIdx.x * BN;
    const int rg = tid >> 4;            // rows rg*8..rg*8+7
    const int cg = tid & 15;            // cols cg*8..cg*8+7
    const int la_m = tid >> 1;          // 0..127
    const int la_k = (tid & 1) << 3;    // 0 or 8
    const int lb_k = tid >> 4;          // 0..15
    const int lb_n = (tid & 15) << 3;   // 0..120

    const float* Arow = A  + (size_t)(m0 + la_m) * E + la_k;
    const float* Brow = Wt + (size_t)lb_k * E + n0 + lb_n;

    float acc[8][8];
    #pragma unroll
    for (int i = 0; i < 8; i++)
        #pragma unroll
        for (int j = 0; j < 8; j++) acc[i][j] = 0.f;

    // prefetched registers
    float4 a0 = *(const float4*)(Arow);
    float4 a1 = *(const float4*)(Arow + 4);
    float4 b0 = *(const float4*)(Brow);
    float4 b1 = *(const float4*)(Brow + 4);

    for (int k0 = 0; k0 < E; k0 += BK) {
        sA[la_k + 0][la_m] = a0.x; sA[la_k + 1][la_m] = a0.y;
        sA[la_k + 2][la_m] = a0.z; sA[la_k + 3][la_m] = a0.w;
        sA[la_k + 4][la_m] = a1.x; sA[la_k + 5][la_m] = a1.y;
        sA[la_k + 6][la_m] = a1.z; sA[la_k + 7][la_m] = a1.w;
        *(float4*)&sB[lb_k][lb_n]     = b0;
        *(float4*)&sB[lb_k][lb_n + 4] = b1;
        __syncthreads();

        float4 na0 = a0, na1 = a1, nb0 = b0, nb1 = b1;
        if (k0 + BK < E) {
            na0 = *(const float4*)(Arow + k0 + BK);
            na1 = *(const float4*)(Arow + k0 + BK + 4);
            nb0 = *(const float4*)(Brow + (size_t)(k0 + BK) * E);
            nb1 = *(const float4*)(Brow + (size_t)(k0 + BK) * E + 4);
        }

        #pragma unroll
        for (int kk = 0; kk < BK; kk++) {
            float4 af0 = *(const float4*)&sA[kk][rg * 8];
            float4 af1 = *(const float4*)&sA[kk][rg * 8 + 4];
            float4 bf0 = *(const float4*)&sB[kk][cg * 8];
            float4 bf1 = *(const float4*)&sB[kk][cg * 8 + 4];
            float a_[8] = {af0.x, af0.y, af0.z, af0.w, af1.x, af1.y, af1.z, af1.w};
            float b_[8] = {bf0.x, bf0.y, bf0.z, bf0.w, bf1.x, bf1.y, bf1.z, bf1.w};
            #pragma unroll
            for (int i = 0; i < 8; i++)
                #pragma unroll
                for (int j = 0; j < 8; j++)
                    acc[i][j] += a_[i] * b_[j];
        }
        __syncthreads();
        a0 = na0; a1 = na1; b0 = nb0; b1 = nb1;
    }

    float4 bv0 = *(const float4*)&bias[n0 + cg * 8];
    float4 bv1 = *(const float4*)&bias[n0 + cg * 8 + 4];
    float bb[8] = {bv0.x, bv0.y, bv0.z, bv0.w, bv1.x, bv1.y, bv1.z, bv1.w};
    #pragma unroll
    for (int i = 0; i < 8; i++) {
        int m = m0 + rg * 8 + i;
        float4 o0, o1;
        o0.x = (acc[i][0] + bb[0]) * scale;
        o0.y = (acc[i][1] + bb[1]) * scale;
        o0.z = (acc[i][2] + bb[2]) * scale;
        o0.w = (acc[i][3] + bb[3]) * scale;
        o1.x = (acc[i][4] + bb[4]) * scale;
        o1.y = (acc[i][5] + bb[5]) * scale;
        o1.z = (acc[i][6] + bb[6]) * scale;
        o1.w = (acc[i][7] + bb[7]) * scale;
        *(float4*)&C[(size_t)m * E + n0 + cg * 8]     = o0;
        *(float4*)&C[(size_t)m * E + n0 + cg * 8 + 4] = o1;
    }
}

// ---------------- lam ----------------
__global__ __launch_bounds__(256) void lam_kernel(
    const float* __restrict__ Wlqc, const float* __restrict__ blqc,
    const float* __restrict__ Wlqq, const float* __restrict__ blqq,
    const float* __restrict__ Wlkc, const float* __restrict__ blkc,
    const float* __restrict__ Wlkk, const float* __restrict__ blkk)
{
    int gw   = (blockIdx.x * blockDim.x + threadIdx.x) >> 5;
    int lane = threadIdx.x & 31;
    if (gw >= S * Hh) return;
    int s = gw / Hh, h = gw % Hh;
    size_t base = (size_t)s * E + h * D;

    float a = g_cq[base + lane] * Wlqc[lane] + g_cq[base + lane + 32] * Wlqc[lane + 32]
            + g_q [base + lane] * Wlqq[lane] + g_q [base + lane + 32] * Wlqq[lane + 32];
    float b = g_ck[base + lane] * Wlkc[lane] + g_ck[base + lane + 32] * Wlkc[lane + 32]
            + g_k [base + lane] * Wlkk[lane] + g_k [base + lane + 32] * Wlkk[lane + 32];
    #pragma unroll
    for (int o = 16; o; o >>= 1) {
        a += __shfl_xor_sync(0xffffffffu, a, o);
        b += __shfl_xor_sync(0xffffffffu, b, o);
    }
    if (lane == 0) {
        float lq = 1.f / (1.f + __expf(-(a + blqc[0] + blqq[0])));
        float lk = 1.f / (1.f + __expf(-(b + blkc[0] + blkk[0])));
        g_lam[gw] = 1.f - lq - lk;
    }
}

// ---------------- QK + softmax + combine, band in registers ----------------
// smem (floats): sQT[64][32], sCQT[64][32], sKT[64][64], sCKT[64][64], sFm[64]
#define KSTR 64
#define QK_SMEM_FLOATS (2048 + 2048 + 64*KSTR + 64*KSTR + 64)

__global__ __launch_bounds__(256, 1) void qk_kernel(
    const int* __restrict__ amask, float* __restrict__ npout)
{
    extern __shared__ float sm[];
    float* sQT  = sm;                  // [64][32]  q^T (pre-scaled)
    float* sCQT = sm + 2048;           // [64][32]  cq^T
    float* sKT  = sm + 4096;           // [64][64]  k^T  ([d][c])
    float* sCKT = sm + 4096 + 4096;    // [64][64]  cq key^T
    float* sFm  = sm + 4096 + 8192;    // [64]

    const int h   = blockIdx.y;
    const int q0  = blockIdx.x * TQ;
    const int tid = threadIdx.x;
    const int rg  = tid >> 4;          // 0..15
    const int cg  = tid & 15;
    const int r0  = rg << 1;           // rows r0, r0+1
    const int c0  = cg << 2;           // cols c0..c0+3 of each 64-block

    // load q/cq transposed (q scaled here; cq pre-scaled by projection)
    {
        int r  = tid >> 3;
        int d0 = (tid & 7) << 3;
        const float4* qp  = (const float4*)(g_q  + (size_t)(q0 + r) * E + h * D + d0);
        const float4* cqp = (const float4*)(g_cq + (size_t)(q0 + r) * E + h * D + d0);
        float4 q1 = qp[0], q2 = qp[1], c1 = cqp[0], c2 = cqp[1];
        sQT[(d0+0)*TQ + r] = q1.x * SCALE; sQT[(d0+1)*TQ + r] = q1.y * SCALE;
        sQT[(d0+2)*TQ + r] = q1.z * SCALE; sQT[(d0+3)*TQ + r] = q1.w * SCALE;
        sQT[(d0+4)*TQ + r] = q2.x * SCALE; sQT[(d0+5)*TQ + r] = q2.y * SCALE;
        sQT[(d0+6)*TQ + r] = q2.z * SCALE; sQT[(d0+7)*TQ + r] = q2.w * SCALE;
        sCQT[(d0+0)*TQ + r] = c1.x; sCQT[(d0+1)*TQ + r] = c1.y;
        sCQT[(d0+2)*TQ + r] = c1.z; sCQT[(d0+3)*TQ + r] = c1.w;
        sCQT[(d0+4)*TQ + r] = c2.x; sCQT[(d0+5)*TQ + r] = c2.y;
        sCQT[(d0+6)*TQ + r] = c2.z; sCQT[(d0+7)*TQ + r] = c2.w;
    }

    float aA[2][NKB*4];   // attn band (then exp values)
    float aQ[2][NKB*4];   // sigmoid(quasi) band

    const int lc  = tid >> 2;          // 0..63 tile-load column (key index)
    const int ld0 = (tid & 3) << 4;    // 0,16,32,48

    #pragma unroll
    for (int b = 0; b < NKB; b++) {
        const int kb0 = q0 - Wb + b * 64;
        __syncthreads();   // protect previous block's smem reads
        {
            int j = kb0 + lc;
            bool ok = (j >= 0) && (j < S);
            const float4* kp = (const float4*)(g_k  + (size_t)(ok ? j : 0) * E + h * D + ld0);
            const float4* cp = (const float4*)(g_cq + (size_t)(ok ? j : 0) * E + h * D + ld0);
            #pragma unroll
            for (int u4 = 0; u4 < 4; u4++) {
                float4 kv = ok ? kp[u4] : make_float4(0.f,0.f,0.f,0.f);
                float4 cv = ok ? cp[u4] : make_float4(0.f,0.f,0.f,0.f);
                int dd = ld0 + u4 * 4;
                sKT [(dd+0)*KSTR + lc] = kv.x; sKT [(dd+1)*KSTR + lc] = kv.y;
                sKT [(dd+2)*KSTR + lc] = kv.z; sKT [(dd+3)*KSTR + lc] = kv.w;
                sCKT[(dd+0)*KSTR + lc] = cv.x; sCKT[(dd+1)*KSTR + lc] = cv.y;
                sCKT[(dd+2)*KSTR + lc] = cv.z; sCKT[(dd+3)*KSTR + lc] = cv.w;
            }
            if (tid < 64) {
                int jj = kb0 + tid;
                sFm[tid] = (jj >= 0 && jj < S && amask[jj] != 0) ? -10000.f : 0.f;
            }
        }
        __syncthreads();

        float acc[2][4] = {{0.f,0.f,0.f,0.f},{0.f,0.f,0.f,0.f}};
        float acq[2][4] = {{0.f,0.f,0.f,0.f},{0.f,0.f,0.f,0.f}};
        #pragma unroll 8
        for (int kk = 0; kk < 64; kk++) {
            float2 qv  = *(const float2*)&sQT [kk*TQ  + r0];
            float2 cqv = *(const float2*)&sCQT[kk*TQ  + r0];
            float4 kv  = *(const float4*)&sKT [kk*KSTR + c0];
            float4 ckv = *(const float4*)&sCKT[kk*KSTR + c0];
            acc[0][0] += qv.x*kv.x;  acc[0][1] += qv.x*kv.y;
            acc[0][2] += qv.x*kv.z;  acc[0][3] += qv.x*kv.w;
            acc[1][0] += qv.y*kv.x;  acc[1][1] += qv.y*kv.y;
            acc[1][2] += qv.y*kv.z;  acc[1][3] += qv.y*kv.w;
            acq[0][0] += cqv.x*ckv.x; acq[0][1] += cqv.x*ckv.y;
            acq[0][2] += cqv.x*ckv.z; acq[0][3] += cqv.x*ckv.w;
            acq[1][0] += cqv.y*ckv.x; acq[1][1] += cqv.y*ckv.y;
            acq[1][2] += cqv.y*ckv.z; acq[1][3] += cqv.y*ckv.w;
        }

        // epilogue into register band
        #pragma unroll
        for (int i = 0; i < 2; i++) {
            int r = r0 + i;
            #pragma unroll
            for (int jx = 0; jx < 4; jx++) {
                int c = c0 + jx;
                int t = b * 64 + c - r;
                int j = kb0 + c;
                bool valid = (t >= 0) && (t <= 512) && (j >= 0) && (j < S);
                float fm = sFm[c];
                aA[i][b*4+jx] = valid ? (acc[i][jx] + fm) : NEGV;
                float sg = 1.f / (1.f + __expf(-(acq[i][jx] + fm)));
                aQ[i][b*4+jx] = valid ? sg : 0.f;
            }
        }
    }

    // softmax + combine + write new_probs (half-warp = one row's 16 col-threads)
    #pragma unroll
    for (int i = 0; i < 2; i++) {
        int r  = r0 + i;
        int ig = q0 + r;
        float m = NEGV;
        #pragma unroll
        for (int x = 0; x < NKB*4; x++) m = fmaxf(m, aA[i][x]);
        #pragma unroll
        for (int o = 8; o; o >>= 1) m = fmaxf(m, __shfl_xor_sync(0xffffffffu, m, o));
        float ssum = 0.f;
        #pragma unroll
        for (int x = 0; x < NKB*4; x++) {
            float e = __expf(aA[i][x] - m);
            aA[i][x] = e;
            ssum += e;
        }
        #pragma unroll
        for (int o = 8; o; o >>= 1) ssum += __shfl_xor_sync(0xffffffffu, ssum, o);
        float inv  = 1.f / ssum;
        float lamv = g_lam[ig * Hh + h];
        bool  qm   = (amask[ig] != 0);
        float* nprow = npout + ((size_t)ig * Hh + h) * TT;
        #pragma unroll
        for (int b = 0; b < NKB; b++) {
            #pragma unroll
            for (int jx = 0; jx < 4; jx++) {
                int t = b * 64 + c0 + jx - r;
                float np = aA[i][b*4+jx] * inv + lamv * aQ[i][b*4+jx];
                if (qm) np = 0.f;
                if (t >= 0 && t <= 512) nprow[t] = np;
            }
        }
    }
}

// ---------------- PV: out = band_pv(new_probs, v) ----------------
#define PSTR 68
#define VSTR 68

__global__ __launch_bounds__(128) void pv_kernel(
    float* __restrict__ outp, const float* __restrict__ npout)
{
    __shared__ float sP[TQ * PSTR];   // [32][68]
    __shared__ float sV[64 * VSTR];   // [64][68]

    const int h   = blockIdx.y;
    const int q0  = blockIdx.x * TQ;
    const int tid = threadIdx.x;
    const int rg  = tid >> 4;         // 0..7 -> rows 4rg..4rg+3
    const int dg  = tid & 15;         // d = 4dg..4dg+3

    float acc[4][4];
    #pragma unroll
    for (int i = 0; i < 4; i++)
        #pragma unroll
        for (int j = 0; j < 4; j++) acc[i][j] = 0.f;

    for (int b = 0; b < NKB; b++) {
        int kb0 = q0 - Wb + b * 64;
        __syncthreads();
        // load p tile: row r, cols c0l..c0l+15
        {
            int r   = tid >> 2;
            int c0l = (tid & 3) << 4;
            const float* nprow = npout + ((size_t)(q0 + r) * Hh + h) * TT;
            #pragma unroll
            for (int x4 = 0; x4 < 4; x4++) {
                int t0 = b * 64 + c0l + x4 * 4 - r;
                float4 pv4;
                pv4.x = (t0+0 >= 0 && t0+0 <= 512) ? nprow[t0+0] : 0.f;
                pv4.y = (t0+1 >= 0 && t0+1 <= 512) ? nprow[t0+1] : 0.f;
                pv4.z = (t0+2 >= 0 && t0+2 <= 512) ? nprow[t0+2] : 0.f;
                pv4.w = (t0+3 >= 0 && t0+3 <= 512) ? nprow[t0+3] : 0.f;
                *(float4*)&sP[r * PSTR + c0l + x4 * 4] = pv4;
            }
        }
        // load v tile [c][d]
        {
            int c   = tid >> 1;
            int d0l = (tid & 1) << 5;
            int j = kb0 + c;
            bool ok = (j >= 0) && (j < S);
            const float4* vp = (const float4*)(g_v + (size_t)(ok ? j : 0) * E + h * D + d0l);
            #pragma unroll
            for (int u4 = 0; u4 < 8; u4++) {
                float4 x = ok ? vp[u4] : make_float4(0.f,0.f,0.f,0.f);
                *(float4*)&sV[c * VSTR + d0l + u4 * 4] = x;
            }
        }
        __syncthreads();

        #pragma unroll 4
        for (int c = 0; c < 64; c++) {
            float4 vv = *(const float4*)&sV[c * VSTR + 4 * dg];
            float p0 = sP[(4*rg+0) * PSTR + c];
            float p1 = sP[(4*rg+1) * PSTR + c];
            float p2 = sP[(4*rg+2) * PSTR + c];
            float p3 = sP[(4*rg+3) * PSTR + c];
            acc[0][0] += p0*vv.x; acc[0][1] += p0*vv.y; acc[0][2] += p0*vv.z; acc[0][3] += p0*vv.w;
            acc[1][0] += p1*vv.x; acc[1][1] += p1*vv.y; acc[1][2] += p1*vv.z; acc[1][3] += p1*vv.w;
            acc[2][0] += p2*vv.x; acc[2][1] += p2*vv.y; acc[2][2] += p2*vv.z; acc[2][3] += p2*vv.w;
            acc[3][0] += p3*vv.x; acc[3][1] += p3*vv.y; acc[3][2] += p3*vv.z; acc[3][3] += p3*vv.w;
        }
    }

    #pragma unroll
    for (int i = 0; i < 4; i++) {
        float4 o;
        o.x = acc[i][0]; o.y = acc[i][1]; o.z = acc[i][2]; o.w = acc[i][3];
        *(float4*)(outp + (size_t)(q0 + 4*rg + i) * E + h * D + 4 * dg) = o;
    }
}

// ---------------- launch ----------------
extern "C" void kernel_launch(void* const* d_in, const int* in_sizes, int n_in,
                              void* d_out, int out_size)
{
    (void)in_sizes; (void)n_in; (void)out_size;

    const float* hs    = (const float*)d_in[0];
    const float* ce    = (const float*)d_in[1];
    const int*   amask = (const int*)  d_in[2];
    // d_in[3] is is_index_masked == (attention_mask != 0); derived from amask.
    const float* Wq   = (const float*)d_in[4];
    const float* bq   = (const float*)d_in[5];
    const float* Wk   = (const float*)d_in[6];
    const float* bk   = (const float*)d_in[7];
    const float* Wv   = (const float*)d_in[8];
    const float* bv   = (const float*)d_in[9];
    const float* Wcq  = (const float*)d_in[10];
    const float* bcq  = (const float*)d_in[11];
    const float* Wck  = (const float*)d_in[12];
    const float* bck  = (const float*)d_in[13];
    const float* Wlqc = (const float*)d_in[14];
    const float* blqc = (const float*)d_in[15];
    const float* Wlqq = (const float*)d_in[16];
    const float* blqq = (const float*)d_in[17];
    const float* Wlkc = (const float*)d_in[18];
    const float* blkc = (const float*)d_in[19];
    const float* Wlkk = (const float*)d_in[20];
    const float* blkk = (const float*)d_in[21];

    float* outp  = (float*)d_out;
    float* npout = outp + (size_t)S * E;   // tuple output: [out | new_probs]

    cudaFuncSetAttribute(qk_kernel, cudaFuncAttributeMaxDynamicSharedMemorySize,
                         QK_SMEM_FLOATS * 4);

    dim3 gg(E / BN, S / BM, 5);
    gemm5_kernel<<<gg, 256>>>(hs, ce, Wq, bq, Wk, bk, Wv, bv, Wcq, bcq, Wck, bck);

    lam_kernel<<<(S * Hh) / 8, 256>>>(Wlqc, blqc, Wlqq, blqq, Wlkc, blkc, Wlkk, blkk);

    qk_kernel<<<dim3(S / TQ, Hh), 256, QK_SMEM_FLOATS * 4>>>(amask, npout);

    pv_kernel<<<dim3(S / TQ, Hh), 128>>>(outp, npout);
}